// round 15
// baseline (speedup 1.0000x reference)
#include <cuda_runtime.h>
#include <cuda_fp16.h>
#include <cuda_fp8.h>
#include <math.h>
#include <stdint.h>

#define NN 100000
#define GG 64
#define ASSETS 50
#define EMAX 1600000

// ---------------- scratch (device globals; no runtime allocation) ----------
__device__ __half2 g_xh   [(size_t)NN * 32];   // 12.8 MB (x fp16)
__device__ __half2 g_agg1h[(size_t)NN * 32];   // 12.8 MB (agg1 fp16)
__device__ __half2 g_h1h  [(size_t)NN * 64];   // 25.6 MB (h1 fp16)
__device__ uint8_t g_h1q  [(size_t)NN * 128];  // 12.8 MB (h1 fp8 e4m3)
__device__ __half2 g_agg2h[(size_t)NN * 64];   // 25.6 MB (agg2 fp16)
__device__ float g_sums[GG * 128];
__device__ int   g_gstart[GG];
__device__ int   g_gend[GG];
// CSR scratch
__device__ int g_deg[NN];
__device__ int g_off[NN + 1];
__device__ int g_cur[NN];
__device__ int g_partials[128];
__device__ int g_sedge[EMAX];

// ---------------- helpers ---------------------------------------------------
__device__ __forceinline__ void mma16(float* d, const uint32_t* a, const uint32_t* b) {
    asm volatile("mma.sync.aligned.m16n8k16.row.col.f32.f16.f16.f32 "
                 "{%0,%1,%2,%3}, {%4,%5,%6,%7}, {%8,%9}, {%0,%1,%2,%3};"
                 : "+f"(d[0]), "+f"(d[1]), "+f"(d[2]), "+f"(d[3])
                 : "r"(a[0]), "r"(a[1]), "r"(a[2]), "r"(a[3]),
                   "r"(b[0]), "r"(b[1]));
}

__device__ __forceinline__ void add2(float4& acc, uint2 u) {
    float2 lo = __half22float2(*(__half2*)&u.x);
    float2 hi = __half22float2(*(__half2*)&u.y);
    acc.x += lo.x; acc.y += lo.y; acc.z += hi.x; acc.w += hi.y;
}

// 8 e4m3 values (uint2) -> accumulate into two float4
__device__ __forceinline__ void add8q(float4& l, float4& h, uint2 u) {
    __half2_raw r0 = __nv_cvt_fp8x2_to_halfraw2((__nv_fp8x2_storage_t)(u.x & 0xffff), __NV_E4M3);
    __half2_raw r1 = __nv_cvt_fp8x2_to_halfraw2((__nv_fp8x2_storage_t)(u.x >> 16),   __NV_E4M3);
    __half2_raw r2 = __nv_cvt_fp8x2_to_halfraw2((__nv_fp8x2_storage_t)(u.y & 0xffff), __NV_E4M3);
    __half2_raw r3 = __nv_cvt_fp8x2_to_halfraw2((__nv_fp8x2_storage_t)(u.y >> 16),   __NV_E4M3);
    float2 p0 = __half22float2(*(__half2*)&r0);
    float2 p1 = __half22float2(*(__half2*)&r1);
    float2 p2 = __half22float2(*(__half2*)&r2);
    float2 p3 = __half22float2(*(__half2*)&r3);
    l.x += p0.x; l.y += p0.y; l.z += p1.x; l.w += p1.y;
    h.x += p2.x; h.y += p2.y; h.z += p3.x; h.w += p3.y;
}

// ---------------- init: zero scratch + convert x -> fp16 ---------------------
__global__ void init_kernel(const float2* __restrict__ x, int n2, int N) {
    int i = blockIdx.x * blockDim.x + threadIdx.x;
    int stride = gridDim.x * blockDim.x;
    for (int j = i; j < n2; j += stride)
        g_xh[j] = __float22half2_rn(x[j]);
    for (int j = i; j < N; j += stride)
        g_deg[j] = 0;
    if (i < GG * 128) g_sums[i] = 0.f;
    if (i < GG) { g_gstart[i] = 0; g_gend[i] = 0; }
}

// ---------------- CSR build --------------------------------------------------
__global__ void hist_kernel(const int* __restrict__ dst, int E) {
    int i = blockIdx.x * blockDim.x + threadIdx.x;
    if (i < E) atomicAdd(&g_deg[dst[i]], 1);
}

__global__ void scan_local(int n) {
    __shared__ int sh[256];
    int t = threadIdx.x;
    int base = blockIdx.x * 1024 + t * 4;
    int v[4];
    #pragma unroll
    for (int i = 0; i < 4; i++) v[i] = (base + i < n) ? g_deg[base + i] : 0;
    int tsum = v[0] + v[1] + v[2] + v[3];
    sh[t] = tsum;
    __syncthreads();
    #pragma unroll
    for (int o = 1; o < 256; o <<= 1) {
        int x = (t >= o) ? sh[t - o] : 0;
        __syncthreads();
        sh[t] += x;
        __syncthreads();
    }
    int excl = sh[t] - tsum;
    if (t == 255) g_partials[blockIdx.x] = sh[255];
    int run = excl;
    #pragma unroll
    for (int i = 0; i < 4; i++) {
        if (base + i < n) { g_off[base + i] = run; run += v[i]; }
    }
}

// scan_add with inlined partials prefix (per-block shared scan of <=128 values)
// also detects per-graph segment boundaries in sorted batch (exact counts)
__global__ void scan_add(int n, int E, const int* __restrict__ batch, int nb) {
    __shared__ int sp[128];
    int t = threadIdx.x;
    if (t < 128) sp[t] = (t < nb) ? g_partials[t] : 0;
    __syncthreads();
    #pragma unroll
    for (int o = 1; o < 128; o <<= 1) {
        int x = (t < 128 && t >= o) ? sp[t - o] : 0;
        __syncthreads();
        if (t < 128) sp[t] += x;
        __syncthreads();
    }
    int i = blockIdx.x * blockDim.x + t;
    if (i < n) {
        int c = i >> 10;
        int v = g_off[i] + (c > 0 ? sp[c - 1] : 0);
        g_off[i] = v;
        g_cur[i] = v;
        int b = batch[i];
        if (i == 0 || batch[i - 1] != b) g_gstart[b] = i;
        if (i == n - 1 || batch[i + 1] != b) g_gend[b] = i + 1;
    }
    if (i == 0) g_off[n] = E;
}

__global__ void fill_csr(const int* __restrict__ src, const int* __restrict__ dst, int E) {
    int i = blockIdx.x * blockDim.x + threadIdx.x;
    if (i < E) {
        int slot = atomicAdd(&g_cur[dst[i]], 1);
        g_sedge[slot] = src[i];
    }
}

// ---------------- CSR gather aggregation -------------------------------------
// Half-warp paired: lanes 0-15 and 16-31 process two different edges in the
// same instruction; 16 lanes cover a full row.
__global__ void gather64h(int N) {
    const uint2* feat = (const uint2*)g_xh;     // row = 16 uint2 = 128 B
    int gtid = blockIdx.x * blockDim.x + threadIdx.x;
    int node = gtid >> 5;
    int lane = gtid & 31;
    if (node >= N) return;
    int half = lane >> 4;
    int sub  = lane & 15;
    int beg = g_off[node];
    int end = g_off[node + 1];
    float4 a0 = make_float4(0.f, 0.f, 0.f, 0.f), a1 = a0, a2 = a0, a3 = a0;
    for (int b = beg; b < end; b += 32) {
        int m = min(32, end - b);
        int s = (lane < m) ? g_sedge[b + lane] : 0;
        int i = 0;
        for (; i + 8 <= m; i += 8) {
            int t0 = __shfl_sync(0xffffffffu, s, i     + half);
            int t1 = __shfl_sync(0xffffffffu, s, i + 2 + half);
            int t2 = __shfl_sync(0xffffffffu, s, i + 4 + half);
            int t3 = __shfl_sync(0xffffffffu, s, i + 6 + half);
            uint2 u0 = feat[(size_t)t0 * 16 + sub];
            uint2 u1 = feat[(size_t)t1 * 16 + sub];
            uint2 u2 = feat[(size_t)t2 * 16 + sub];
            uint2 u3 = feat[(size_t)t3 * 16 + sub];
            add2(a0, u0); add2(a1, u1); add2(a2, u2); add2(a3, u3);
        }
        for (; i + 2 <= m; i += 2) {
            int t0 = __shfl_sync(0xffffffffu, s, i + half);
            uint2 u0 = feat[(size_t)t0 * 16 + sub];
            add2(a0, u0);
        }
        if (i < m) {
            int t0 = __shfl_sync(0xffffffffu, s, i);
            if (half == 0) {
                uint2 u0 = feat[(size_t)t0 * 16 + sub];
                add2(a0, u0);
            }
        }
    }
    float4 r;
    r.x = (a0.x + a1.x) + (a2.x + a3.x);
    r.y = (a0.y + a1.y) + (a2.y + a3.y);
    r.z = (a0.z + a1.z) + (a2.z + a3.z);
    r.w = (a0.w + a1.w) + (a2.w + a3.w);
    r.x += __shfl_down_sync(0xffffffffu, r.x, 16);
    r.y += __shfl_down_sync(0xffffffffu, r.y, 16);
    r.z += __shfl_down_sync(0xffffffffu, r.z, 16);
    r.w += __shfl_down_sync(0xffffffffu, r.w, 16);
    if (half == 0) {
        uint2 o;
        *(__half2*)&o.x = __float22half2_rn(make_float2(r.x, r.y));
        *(__half2*)&o.y = __float22half2_rn(make_float2(r.z, r.w));
        ((uint2*)g_agg1h)[(size_t)node * 16 + sub] = o;
    }
}

// layer-2 gather reads fp8 h1 (row = 128 B = 16 uint2), writes fp16 agg2
__global__ void gather128q(int N) {
    const uint2* feat = (const uint2*)g_h1q;
    int gtid = blockIdx.x * blockDim.x + threadIdx.x;
    int node = gtid >> 5;
    int lane = gtid & 31;
    if (node >= N) return;
    int half = lane >> 4;
    int sub  = lane & 15;
    int beg = g_off[node];
    int end = g_off[node + 1];
    float4 l0 = make_float4(0.f, 0.f, 0.f, 0.f), h0 = l0;
    float4 l1 = l0, h1 = l0, l2 = l0, h2 = l0, l3 = l0, h3 = l0;
    for (int b = beg; b < end; b += 32) {
        int m = min(32, end - b);
        int s = (lane < m) ? g_sedge[b + lane] : 0;
        int i = 0;
        for (; i + 8 <= m; i += 8) {
            int t0 = __shfl_sync(0xffffffffu, s, i     + half);
            int t1 = __shfl_sync(0xffffffffu, s, i + 2 + half);
            int t2 = __shfl_sync(0xffffffffu, s, i + 4 + half);
            int t3 = __shfl_sync(0xffffffffu, s, i + 6 + half);
            uint2 u0 = feat[(size_t)t0 * 16 + sub];
            uint2 u1 = feat[(size_t)t1 * 16 + sub];
            uint2 u2 = feat[(size_t)t2 * 16 + sub];
            uint2 u3 = feat[(size_t)t3 * 16 + sub];
            add8q(l0, h0, u0); add8q(l1, h1, u1);
            add8q(l2, h2, u2); add8q(l3, h3, u3);
        }
        for (; i + 2 <= m; i += 2) {
            int t0 = __shfl_sync(0xffffffffu, s, i + half);
            uint2 u0 = feat[(size_t)t0 * 16 + sub];
            add8q(l0, h0, u0);
        }
        if (i < m) {
            int t0 = __shfl_sync(0xffffffffu, s, i);
            if (half == 0) {
                uint2 u0 = feat[(size_t)t0 * 16 + sub];
                add8q(l0, h0, u0);
            }
        }
    }
    float4 rl, rh;
    rl.x = (l0.x + l1.x) + (l2.x + l3.x);
    rl.y = (l0.y + l1.y) + (l2.y + l3.y);
    rl.z = (l0.z + l1.z) + (l2.z + l3.z);
    rl.w = (l0.w + l1.w) + (l2.w + l3.w);
    rh.x = (h0.x + h1.x) + (h2.x + h3.x);
    rh.y = (h0.y + h1.y) + (h2.y + h3.y);
    rh.z = (h0.z + h1.z) + (h2.z + h3.z);
    rh.w = (h0.w + h1.w) + (h2.w + h3.w);
    rl.x += __shfl_down_sync(0xffffffffu, rl.x, 16);
    rl.y += __shfl_down_sync(0xffffffffu, rl.y, 16);
    rl.z += __shfl_down_sync(0xffffffffu, rl.z, 16);
    rl.w += __shfl_down_sync(0xffffffffu, rl.w, 16);
    rh.x += __shfl_down_sync(0xffffffffu, rh.x, 16);
    rh.y += __shfl_down_sync(0xffffffffu, rh.y, 16);
    rh.z += __shfl_down_sync(0xffffffffu, rh.z, 16);
    rh.w += __shfl_down_sync(0xffffffffu, rh.w, 16);
    if (half == 0) {
        // 8 consecutive features per lane -> uint4 of 4 half2
        uint4 o;
        *(__half2*)&o.x = __float22half2_rn(make_float2(rl.x, rl.y));
        *(__half2*)&o.y = __float22half2_rn(make_float2(rl.z, rl.w));
        *(__half2*)&o.z = __float22half2_rn(make_float2(rh.x, rh.y));
        *(__half2*)&o.w = __float22half2_rn(make_float2(rh.z, rh.w));
        ((uint4*)g_agg2h)[(size_t)node * 16 + sub] = o;
    }
}

// ---------------- fused dual GEMM (fp16 tensor cores) + bias + relu ----------
// POOL=true: epilogue does segmented mean-pool into g_sums (batch sorted).
// outq (POOL=false only): also emit fp8 e4m3 copy of output.
template<int K, bool PF, bool POOL>
__global__ void __launch_bounds__(256)
gemm_dual_fp16(const __half* __restrict__ A, const __half* __restrict__ B,
               const float* __restrict__ wA, const float* __restrict__ wB,
               const float* __restrict__ bias, __half2* __restrict__ out,
               uint8_t* __restrict__ outq,
               const int* __restrict__ batch, int N, int num_tiles) {
    constexpr int U   = K + 4;             // row stride in uint32
    constexpr int QP4 = K / 8;             // uint4 per row per matrix
    constexpr int PER = (64 * QP4) / 256;

    extern __shared__ uint32_t smem_u[];
    uint32_t* sW  = smem_u;                // [128][U]
    uint32_t* sIn = smem_u + 128 * U;      // [64][U]
    float*    sInF = (float*)sIn;          // aliased fp32 tile for pooling
    __shared__ int sb[64];

    const int tid  = threadIdx.x;
    const int lane = tid & 31;
    const int wid  = tid >> 5;
    const int wm   = wid & 1;
    const int wn   = wid >> 1;

    // stage weights once: fp32 gmem -> fp16 smem, transposed n-major
    {
        __half* sWh = (__half*)sW;
        for (int idx = tid; idx < K * 128; idx += 256) {
            int k = idx >> 7;
            int n = idx & 127;
            sWh[n * (2 * U) + k]     = __float2half_rn(wA[idx]);
            sWh[n * (2 * U) + K + k] = __float2half_rn(wB[idx]);
        }
    }

    uint4 pa[PER], pb[PER];

    auto loadTile = [&](int tile) {
        #pragma unroll
        for (int i = 0; i < PER; i++) {
            int idx = tid + i * 256;
            int r = idx / QP4, q = idx % QP4;
            int grow = tile * 64 + r;
            if (tile < num_tiles && grow < N) {
                pa[i] = ((const uint4*)(A + (size_t)grow * K))[q];
                pb[i] = ((const uint4*)(B + (size_t)grow * K))[q];
            } else {
                pa[i] = make_uint4(0u, 0u, 0u, 0u);
                pb[i] = pa[i];
            }
        }
    };
    auto storeTile = [&]() {
        #pragma unroll
        for (int i = 0; i < PER; i++) {
            int idx = tid + i * 256;
            int r = idx / QP4, q = idx % QP4;
            *(uint4*)&sIn[r * U + q * 4]            = pa[i];
            *(uint4*)&sIn[r * U + (K >> 1) + q * 4] = pb[i];
        }
    };

    loadTile(blockIdx.x);
    __syncthreads();
    storeTile();
    __syncthreads();

    const int fr = lane >> 2;
    const int fc = lane & 3;

    for (int tile = blockIdx.x; tile < num_tiles; tile += gridDim.x) {
        const int row0 = tile << 6;
        const int ntile = tile + gridDim.x;

        if (PF && ntile < num_tiles) loadTile(ntile);

        float acc[2][4][4] = {};
        const uint32_t* sInW = sIn + (wm * 32) * U;
        const uint32_t* sWW  = sW  + (wn * 32) * U;

        #pragma unroll 4
        for (int kw = 0; kw < K; kw += 8) {
            uint32_t a[2][4];
            #pragma unroll
            for (int mt = 0; mt < 2; mt++) {
                const uint32_t* p = sInW + (mt * 16 + fr) * U + kw + fc;
                a[mt][0] = p[0];
                a[mt][1] = p[8 * U];
                a[mt][2] = p[4];
                a[mt][3] = p[8 * U + 4];
            }
            uint32_t b[4][2];
            #pragma unroll
            for (int nt = 0; nt < 4; nt++) {
                const uint32_t* p = sWW + (nt * 8 + fr) * U + kw + fc;
                b[nt][0] = p[0];
                b[nt][1] = p[4];
            }
            #pragma unroll
            for (int mt = 0; mt < 2; mt++)
                #pragma unroll
                for (int nt = 0; nt < 4; nt++)
                    mma16(acc[mt][nt], a[mt], b[nt]);
        }

        __syncthreads();   // done reading sIn

        if (POOL) {
            if (tid < 64) {
                int rr = row0 + tid;
                sb[tid] = (rr < N) ? batch[rr] : -1;
            }
            #pragma unroll
            for (int mt = 0; mt < 2; mt++) {
                int lr = wm * 32 + mt * 16 + fr;
                #pragma unroll
                for (int nt = 0; nt < 4; nt++) {
                    int col = wn * 32 + nt * 8 + 2 * fc;
                    float2 bb = *(const float2*)&bias[col];
                    float2 o0, o1;
                    o0.x = fmaxf(acc[mt][nt][0] + bb.x, 0.f);
                    o0.y = fmaxf(acc[mt][nt][1] + bb.y, 0.f);
                    o1.x = fmaxf(acc[mt][nt][2] + bb.x, 0.f);
                    o1.y = fmaxf(acc[mt][nt][3] + bb.y, 0.f);
                    *(float2*)&sInF[lr * 130 + col]       = o0;
                    *(float2*)&sInF[(lr + 8) * 130 + col] = o1;
                }
            }
            __syncthreads();
            {
                int m = min(64, N - row0);
                int col  = tid & 127;
                int half = tid >> 7;
                int rs = half * 32;
                int re = min(m, rs + 32);
                if (rs < re) {
                    float acs = 0.f;
                    int cur = sb[rs];
                    for (int r = rs; r < re; r++) {
                        int g = sb[r];
                        float v = sInF[r * 130 + col];
                        if (g != cur) {
                            atomicAdd(&g_sums[cur * 128 + col], acs);
                            acs = 0.f; cur = g;
                        }
                        acs += v;
                    }
                    atomicAdd(&g_sums[cur * 128 + col], acs);
                }
            }
            __syncthreads();
            if (ntile < num_tiles) {
                if (!PF) loadTile(ntile);
                storeTile();
            }
            __syncthreads();
        } else {
            if (ntile < num_tiles) {
                if (!PF) loadTile(ntile);
                storeTile();
            }
            __syncthreads();
            #pragma unroll
            for (int mt = 0; mt < 2; mt++) {
                int r1 = row0 + wm * 32 + mt * 16 + fr;
                #pragma unroll
                for (int nt = 0; nt < 4; nt++) {
                    int col = wn * 32 + nt * 8 + 2 * fc;
                    float2 bb = *(const float2*)&bias[col];
                    if (r1 < N) {
                        float2 o;
                        o.x = fmaxf(acc[mt][nt][0] + bb.x, 0.f);
                        o.y = fmaxf(acc[mt][nt][1] + bb.y, 0.f);
                        out[(size_t)r1 * 64 + (col >> 1)] = __float22half2_rn(o);
                        if (outq) {
                            __nv_fp8x2_storage_t q =
                                __nv_cvt_float2_to_fp8x2(o, __NV_SATFINITE, __NV_E4M3);
                            *(uint16_t*)&outq[(size_t)r1 * 128 + col] = (uint16_t)q;
                        }
                    }
                    if (r1 + 8 < N) {
                        float2 o;
                        o.x = fmaxf(acc[mt][nt][2] + bb.x, 0.f);
                        o.y = fmaxf(acc[mt][nt][3] + bb.y, 0.f);
                        out[(size_t)(r1 + 8) * 64 + (col >> 1)] = __float22half2_rn(o);
                        if (outq) {
                            __nv_fp8x2_storage_t q =
                                __nv_cvt_float2_to_fp8x2(o, __NV_SATFINITE, __NV_E4M3);
                            *(uint16_t*)&outq[(size_t)(r1 + 8) * 128 + col] = (uint16_t)q;
                        }
                    }
                }
            }
        }
    }
}

// ---------------- MLP head + softmax (one block per graph) -------------------
__global__ void head_kernel(const float* __restrict__ fc1w, const float* __restrict__ fc1b,
                            const float* __restrict__ fc2w, const float* __restrict__ fc2b,
                            float* __restrict__ out) {
    __shared__ float p[128];
    __shared__ float hdn[128];
    __shared__ float lg[ASSETS];
    __shared__ float smax, ssum;
    int g = blockIdx.x, t = threadIdx.x;

    float cnt = fmaxf((float)(g_gend[g] - g_gstart[g]), 1.f);
    p[t] = g_sums[g * 128 + t] / cnt;
    __syncthreads();

    float a = fc1b[t];
    #pragma unroll 8
    for (int k = 0; k < 128; k++) a = fmaf(p[k], fc1w[k * 128 + t], a);
    hdn[t] = fmaxf(a, 0.f);
    __syncthreads();

    float logit = 0.f;
    if (t < ASSETS) {
        logit = fc2b[t];
        #pragma unroll 8
        for (int k = 0; k < 128; k++) logit = fmaf(hdn[k], fc2w[k * ASSETS + t], logit);
        lg[t] = logit;
    }
    __syncthreads();
    if (t == 0) {
        float m = -1e30f;
        for (int i = 0; i < ASSETS; i++) m = fmaxf(m, lg[i]);
        smax = m;
    }
    __syncthreads();
    float e = 0.f;
    if (t < ASSETS) { e = expf(logit - smax); lg[t] = e; }
    __syncthreads();
    if (t == 0) {
        float s = 0.f;
        for (int i = 0; i < ASSETS; i++) s += lg[i];
        ssum = s;
    }
    __syncthreads();
    if (t < ASSETS) out[g * ASSETS + t] = lg[t] / ssum;
}

// ---------------- launch -----------------------------------------------------
extern "C" void kernel_launch(void* const* d_in, const int* in_sizes, int n_in,
                              void* d_out, int out_size) {
    const float* x       = (const float*)d_in[0];
    const int*   ei      = (const int*)d_in[1];
    const int*   batch   = (const int*)d_in[2];
    const float* w1_rel  = (const float*)d_in[3];
    const float* b1      = (const float*)d_in[4];
    const float* w1_root = (const float*)d_in[5];
    const float* w2_rel  = (const float*)d_in[6];
    const float* b2      = (const float*)d_in[7];
    const float* w2_root = (const float*)d_in[8];
    const float* fc1w    = (const float*)d_in[9];
    const float* fc1b    = (const float*)d_in[10];
    const float* fc2w    = (const float*)d_in[11];
    const float* fc2b    = (const float*)d_in[12];
    float*       out     = (float*)d_out;

    const int N = in_sizes[2];        // 100000
    const int E = in_sizes[1] / 2;    // 1600000
    const int* src = ei;
    const int* dst = ei + E;

    void *xh, *agg1h, *h1h, *h1q, *agg2h;
    cudaGetSymbolAddress(&xh,    g_xh);
    cudaGetSymbolAddress(&agg1h, g_agg1h);
    cudaGetSymbolAddress(&h1h,   g_h1h);
    cudaGetSymbolAddress(&h1q,   g_h1q);
    cudaGetSymbolAddress(&agg2h, g_agg2h);

    const int SMEM1 = 192 * (64  + 4) * 4;   // 52224 B
    const int SMEM2 = 192 * (128 + 4) * 4;   // 101376 B
    cudaFuncSetAttribute((const void*)gemm_dual_fp16<64, true, false>,
                         cudaFuncAttributeMaxDynamicSharedMemorySize, SMEM1);
    cudaFuncSetAttribute((const void*)gemm_dual_fp16<128, true, true>,
                         cudaFuncAttributeMaxDynamicSharedMemorySize, SMEM2);

    // ---- init + CSR build ----
    init_kernel<<<512, 256>>>((const float2*)x, N * 32, N);
    hist_kernel<<<(E + 255) / 256, 256>>>(dst, E);
    int nscan = (N + 1023) / 1024;
    scan_local<<<nscan, 256>>>(N);
    scan_add<<<(N + 255) / 256, 256>>>(N, E, batch, nscan);
    fill_csr<<<(E + 255) / 256, 256>>>(src, dst, E);

    // ---- layer 1 ----
    int gblocks = (N * 32 + 255) / 256;
    gather64h<<<gblocks, 256>>>(N);

    int tiles = (N + 63) / 64;
    int grid = tiles < 296 ? tiles : 296;
    gemm_dual_fp16<64, true, false><<<grid, 256, SMEM1>>>(
        (const __half*)agg1h, (const __half*)xh, w1_rel, w1_root, b1,
        (__half2*)h1h, (uint8_t*)h1q, nullptr, N, tiles);

    // ---- layer 2 (fp8 gather, pool fused into epilogue) ----
    gather128q<<<gblocks, 256>>>(N);

    gemm_dual_fp16<128, true, true><<<grid, 256, SMEM2>>>(
        (const __half*)agg2h, (const __half*)h1h, w2_rel, w2_root, b2,
        nullptr, nullptr, batch, N, tiles);

    // ---- head ----
    head_kernel<<<GG, 128>>>(fc1w, fc1b, fc2w, fc2b, out);
}

// round 16
// speedup vs baseline: 1.0782x; 1.0782x over previous
#include <cuda_runtime.h>
#include <cuda_fp16.h>
#include <math.h>
#include <stdint.h>

#define NN 100000
#define GG 64
#define ASSETS 50
#define EMAX 1600000

// ---------------- scratch (device globals; no runtime allocation) ----------
__device__ __half2 g_xh   [(size_t)NN * 32];   // 12.8 MB (x fp16)
__device__ __half2 g_agg1h[(size_t)NN * 32];   // 12.8 MB (agg1 fp16)
__device__ __half2 g_h1h  [(size_t)NN * 64];   // 25.6 MB (h1 fp16)
__device__ __half2 g_agg2h[(size_t)NN * 64];   // 25.6 MB (agg2 fp16)
__device__ float g_sums[GG * 128];
__device__ int   g_gstart[GG];
__device__ int   g_gend[GG];
// CSR scratch
__device__ int g_deg[NN];
__device__ int g_off[NN + 1];
__device__ int g_cur[NN];
__device__ int g_partials[128];
__device__ int g_sedge[EMAX];

// ---------------- helpers ---------------------------------------------------
__device__ __forceinline__ void mma16(float* d, const uint32_t* a, const uint32_t* b) {
    asm volatile("mma.sync.aligned.m16n8k16.row.col.f32.f16.f16.f32 "
                 "{%0,%1,%2,%3}, {%4,%5,%6,%7}, {%8,%9}, {%0,%1,%2,%3};"
                 : "+f"(d[0]), "+f"(d[1]), "+f"(d[2]), "+f"(d[3])
                 : "r"(a[0]), "r"(a[1]), "r"(a[2]), "r"(a[3]),
                   "r"(b[0]), "r"(b[1]));
}

__device__ __forceinline__ void add2(float4& acc, uint2 u) {
    float2 lo = __half22float2(*(__half2*)&u.x);
    float2 hi = __half22float2(*(__half2*)&u.y);
    acc.x += lo.x; acc.y += lo.y; acc.z += hi.x; acc.w += hi.y;
}
__device__ __forceinline__ void add4(float4& l, float4& h, uint4 u) {
    float2 p0 = __half22float2(*(__half2*)&u.x);
    float2 p1 = __half22float2(*(__half2*)&u.y);
    float2 p2 = __half22float2(*(__half2*)&u.z);
    float2 p3 = __half22float2(*(__half2*)&u.w);
    l.x += p0.x; l.y += p0.y; l.z += p1.x; l.w += p1.y;
    h.x += p2.x; h.y += p2.y; h.z += p3.x; h.w += p3.y;
}

// ---------------- init: zero scratch + convert x -> fp16 ---------------------
__global__ void init_kernel(const float2* __restrict__ x, int n2, int N) {
    int i = blockIdx.x * blockDim.x + threadIdx.x;
    int stride = gridDim.x * blockDim.x;
    for (int j = i; j < n2; j += stride)
        g_xh[j] = __float22half2_rn(x[j]);
    for (int j = i; j < N; j += stride)
        g_deg[j] = 0;
    if (i < GG * 128) g_sums[i] = 0.f;
    if (i < GG) { g_gstart[i] = 0; g_gend[i] = 0; }
}

// ---------------- CSR build --------------------------------------------------
__global__ void hist_kernel(const int* __restrict__ dst, int E) {
    int i = blockIdx.x * blockDim.x + threadIdx.x;
    if (i < E) atomicAdd(&g_deg[dst[i]], 1);
}

__global__ void scan_local(int n) {
    __shared__ int sh[256];
    int t = threadIdx.x;
    int base = blockIdx.x * 1024 + t * 4;
    int v[4];
    #pragma unroll
    for (int i = 0; i < 4; i++) v[i] = (base + i < n) ? g_deg[base + i] : 0;
    int tsum = v[0] + v[1] + v[2] + v[3];
    sh[t] = tsum;
    __syncthreads();
    #pragma unroll
    for (int o = 1; o < 256; o <<= 1) {
        int x = (t >= o) ? sh[t - o] : 0;
        __syncthreads();
        sh[t] += x;
        __syncthreads();
    }
    int excl = sh[t] - tsum;
    if (t == 255) g_partials[blockIdx.x] = sh[255];
    int run = excl;
    #pragma unroll
    for (int i = 0; i < 4; i++) {
        if (base + i < n) { g_off[base + i] = run; run += v[i]; }
    }
}

// scan_add with inlined partials prefix (per-block shared scan of <=128 values)
// also detects per-graph segment boundaries in sorted batch (exact counts)
__global__ void scan_add(int n, int E, const int* __restrict__ batch, int nb) {
    __shared__ int sp[128];
    int t = threadIdx.x;
    if (t < 128) sp[t] = (t < nb) ? g_partials[t] : 0;
    __syncthreads();
    #pragma unroll
    for (int o = 1; o < 128; o <<= 1) {
        int x = (t < 128 && t >= o) ? sp[t - o] : 0;
        __syncthreads();
        if (t < 128) sp[t] += x;
        __syncthreads();
    }
    int i = blockIdx.x * blockDim.x + t;
    if (i < n) {
        int c = i >> 10;
        int v = g_off[i] + (c > 0 ? sp[c - 1] : 0);
        g_off[i] = v;
        g_cur[i] = v;
        int b = batch[i];
        if (i == 0 || batch[i - 1] != b) g_gstart[b] = i;
        if (i == n - 1 || batch[i + 1] != b) g_gend[b] = i + 1;
    }
    if (i == 0) g_off[n] = E;
}

__global__ void fill_csr(const int* __restrict__ src, const int* __restrict__ dst, int E) {
    int i = blockIdx.x * blockDim.x + threadIdx.x;
    if (i < E) {
        int slot = atomicAdd(&g_cur[dst[i]], 1);
        g_sedge[slot] = src[i];
    }
}

// ---------------- CSR gather aggregation (fp16, fp32 acc) --------------------
// Half-warp paired: lanes 0-15 and 16-31 process two different edges in the
// same instruction; 16 lanes cover a full row.
__global__ void gather64h(int N) {
    const uint2* feat = (const uint2*)g_xh;     // row = 16 uint2 = 128 B
    int gtid = blockIdx.x * blockDim.x + threadIdx.x;
    int node = gtid >> 5;
    int lane = gtid & 31;
    if (node >= N) return;
    int half = lane >> 4;
    int sub  = lane & 15;
    int beg = g_off[node];
    int end = g_off[node + 1];
    float4 a0 = make_float4(0.f, 0.f, 0.f, 0.f), a1 = a0, a2 = a0, a3 = a0;
    for (int b = beg; b < end; b += 32) {
        int m = min(32, end - b);
        int s = (lane < m) ? g_sedge[b + lane] : 0;
        int i = 0;
        for (; i + 8 <= m; i += 8) {
            int t0 = __shfl_sync(0xffffffffu, s, i     + half);
            int t1 = __shfl_sync(0xffffffffu, s, i + 2 + half);
            int t2 = __shfl_sync(0xffffffffu, s, i + 4 + half);
            int t3 = __shfl_sync(0xffffffffu, s, i + 6 + half);
            uint2 u0 = feat[(size_t)t0 * 16 + sub];
            uint2 u1 = feat[(size_t)t1 * 16 + sub];
            uint2 u2 = feat[(size_t)t2 * 16 + sub];
            uint2 u3 = feat[(size_t)t3 * 16 + sub];
            add2(a0, u0); add2(a1, u1); add2(a2, u2); add2(a3, u3);
        }
        for (; i + 2 <= m; i += 2) {
            int t0 = __shfl_sync(0xffffffffu, s, i + half);
            uint2 u0 = feat[(size_t)t0 * 16 + sub];
            add2(a0, u0);
        }
        if (i < m) {
            int t0 = __shfl_sync(0xffffffffu, s, i);
            if (half == 0) {
                uint2 u0 = feat[(size_t)t0 * 16 + sub];
                add2(a0, u0);
            }
        }
    }
    float4 r;
    r.x = (a0.x + a1.x) + (a2.x + a3.x);
    r.y = (a0.y + a1.y) + (a2.y + a3.y);
    r.z = (a0.z + a1.z) + (a2.z + a3.z);
    r.w = (a0.w + a1.w) + (a2.w + a3.w);
    r.x += __shfl_down_sync(0xffffffffu, r.x, 16);
    r.y += __shfl_down_sync(0xffffffffu, r.y, 16);
    r.z += __shfl_down_sync(0xffffffffu, r.z, 16);
    r.w += __shfl_down_sync(0xffffffffu, r.w, 16);
    if (half == 0) {
        uint2 o;
        *(__half2*)&o.x = __float22half2_rn(make_float2(r.x, r.y));
        *(__half2*)&o.y = __float22half2_rn(make_float2(r.z, r.w));
        ((uint2*)g_agg1h)[(size_t)node * 16 + sub] = o;
    }
}

__global__ void gather128h(int N) {
    const uint4* feat = (const uint4*)g_h1h;    // row = 16 uint4 = 256 B
    int gtid = blockIdx.x * blockDim.x + threadIdx.x;
    int node = gtid >> 5;
    int lane = gtid & 31;
    if (node >= N) return;
    int half = lane >> 4;
    int sub  = lane & 15;
    int beg = g_off[node];
    int end = g_off[node + 1];
    float4 l0 = make_float4(0.f, 0.f, 0.f, 0.f), h0 = l0;
    float4 l1 = l0, h1 = l0, l2 = l0, h2 = l0, l3 = l0, h3 = l0;
    for (int b = beg; b < end; b += 32) {
        int m = min(32, end - b);
        int s = (lane < m) ? g_sedge[b + lane] : 0;
        int i = 0;
        for (; i + 8 <= m; i += 8) {
            int t0 = __shfl_sync(0xffffffffu, s, i     + half);
            int t1 = __shfl_sync(0xffffffffu, s, i + 2 + half);
            int t2 = __shfl_sync(0xffffffffu, s, i + 4 + half);
            int t3 = __shfl_sync(0xffffffffu, s, i + 6 + half);
            uint4 u0 = feat[(size_t)t0 * 16 + sub];
            uint4 u1 = feat[(size_t)t1 * 16 + sub];
            uint4 u2 = feat[(size_t)t2 * 16 + sub];
            uint4 u3 = feat[(size_t)t3 * 16 + sub];
            add4(l0, h0, u0); add4(l1, h1, u1);
            add4(l2, h2, u2); add4(l3, h3, u3);
        }
        for (; i + 2 <= m; i += 2) {
            int t0 = __shfl_sync(0xffffffffu, s, i + half);
            uint4 u0 = feat[(size_t)t0 * 16 + sub];
            add4(l0, h0, u0);
        }
        if (i < m) {
            int t0 = __shfl_sync(0xffffffffu, s, i);
            if (half == 0) {
                uint4 u0 = feat[(size_t)t0 * 16 + sub];
                add4(l0, h0, u0);
            }
        }
    }
    float4 rl, rh;
    rl.x = (l0.x + l1.x) + (l2.x + l3.x);
    rl.y = (l0.y + l1.y) + (l2.y + l3.y);
    rl.z = (l0.z + l1.z) + (l2.z + l3.z);
    rl.w = (l0.w + l1.w) + (l2.w + l3.w);
    rh.x = (h0.x + h1.x) + (h2.x + h3.x);
    rh.y = (h0.y + h1.y) + (h2.y + h3.y);
    rh.z = (h0.z + h1.z) + (h2.z + h3.z);
    rh.w = (h0.w + h1.w) + (h2.w + h3.w);
    rl.x += __shfl_down_sync(0xffffffffu, rl.x, 16);
    rl.y += __shfl_down_sync(0xffffffffu, rl.y, 16);
    rl.z += __shfl_down_sync(0xffffffffu, rl.z, 16);
    rl.w += __shfl_down_sync(0xffffffffu, rl.w, 16);
    rh.x += __shfl_down_sync(0xffffffffu, rh.x, 16);
    rh.y += __shfl_down_sync(0xffffffffu, rh.y, 16);
    rh.z += __shfl_down_sync(0xffffffffu, rh.z, 16);
    rh.w += __shfl_down_sync(0xffffffffu, rh.w, 16);
    if (half == 0) {
        uint4 o;
        *(__half2*)&o.x = __float22half2_rn(make_float2(rl.x, rl.y));
        *(__half2*)&o.y = __float22half2_rn(make_float2(rl.z, rl.w));
        *(__half2*)&o.z = __float22half2_rn(make_float2(rh.x, rh.y));
        *(__half2*)&o.w = __float22half2_rn(make_float2(rh.z, rh.w));
        ((uint4*)g_agg2h)[(size_t)node * 16 + sub] = o;
    }
}

// ---------------- fused dual GEMM (fp16 tensor cores) + bias + relu ----------
// POOL=true: epilogue does segmented mean-pool into g_sums (batch sorted).
template<int K, bool PF, bool POOL>
__global__ void __launch_bounds__(256)
gemm_dual_fp16(const __half* __restrict__ A, const __half* __restrict__ B,
               const float* __restrict__ wA, const float* __restrict__ wB,
               const float* __restrict__ bias, __half2* __restrict__ out,
               const int* __restrict__ batch, int N, int num_tiles) {
    constexpr int U   = K + 4;             // row stride in uint32
    constexpr int QP4 = K / 8;             // uint4 per row per matrix
    constexpr int PER = (64 * QP4) / 256;

    extern __shared__ uint32_t smem_u[];
    uint32_t* sW  = smem_u;                // [128][U]
    uint32_t* sIn = smem_u + 128 * U;      // [64][U]
    float*    sInF = (float*)sIn;          // aliased fp32 tile for pooling
    __shared__ int sb[64];

    const int tid  = threadIdx.x;
    const int lane = tid & 31;
    const int wid  = tid >> 5;
    const int wm   = wid & 1;
    const int wn   = wid >> 1;

    // stage weights once: fp32 gmem -> fp16 smem, transposed n-major
    {
        __half* sWh = (__half*)sW;
        for (int idx = tid; idx < K * 128; idx += 256) {
            int k = idx >> 7;
            int n = idx & 127;
            sWh[n * (2 * U) + k]     = __float2half_rn(wA[idx]);
            sWh[n * (2 * U) + K + k] = __float2half_rn(wB[idx]);
        }
    }

    uint4 pa[PER], pb[PER];

    auto loadTile = [&](int tile) {
        #pragma unroll
        for (int i = 0; i < PER; i++) {
            int idx = tid + i * 256;
            int r = idx / QP4, q = idx % QP4;
            int grow = tile * 64 + r;
            if (tile < num_tiles && grow < N) {
                pa[i] = ((const uint4*)(A + (size_t)grow * K))[q];
                pb[i] = ((const uint4*)(B + (size_t)grow * K))[q];
            } else {
                pa[i] = make_uint4(0u, 0u, 0u, 0u);
                pb[i] = pa[i];
            }
        }
    };
    auto storeTile = [&]() {
        #pragma unroll
        for (int i = 0; i < PER; i++) {
            int idx = tid + i * 256;
            int r = idx / QP4, q = idx % QP4;
            *(uint4*)&sIn[r * U + q * 4]            = pa[i];
            *(uint4*)&sIn[r * U + (K >> 1) + q * 4] = pb[i];
        }
    };

    loadTile(blockIdx.x);
    __syncthreads();
    storeTile();
    __syncthreads();

    const int fr = lane >> 2;
    const int fc = lane & 3;

    for (int tile = blockIdx.x; tile < num_tiles; tile += gridDim.x) {
        const int row0 = tile << 6;
        const int ntile = tile + gridDim.x;

        if (PF && ntile < num_tiles) loadTile(ntile);

        float acc[2][4][4] = {};
        const uint32_t* sInW = sIn + (wm * 32) * U;
        const uint32_t* sWW  = sW  + (wn * 32) * U;

        #pragma unroll 4
        for (int kw = 0; kw < K; kw += 8) {
            uint32_t a[2][4];
            #pragma unroll
            for (int mt = 0; mt < 2; mt++) {
                const uint32_t* p = sInW + (mt * 16 + fr) * U + kw + fc;
                a[mt][0] = p[0];
                a[mt][1] = p[8 * U];
                a[mt][2] = p[4];
                a[mt][3] = p[8 * U + 4];
            }
            uint32_t b[4][2];
            #pragma unroll
            for (int nt = 0; nt < 4; nt++) {
                const uint32_t* p = sWW + (nt * 8 + fr) * U + kw + fc;
                b[nt][0] = p[0];
                b[nt][1] = p[4];
            }
            #pragma unroll
            for (int mt = 0; mt < 2; mt++)
                #pragma unroll
                for (int nt = 0; nt < 4; nt++)
                    mma16(acc[mt][nt], a[mt], b[nt]);
        }

        __syncthreads();   // done reading sIn

        if (POOL) {
            if (tid < 64) {
                int rr = row0 + tid;
                sb[tid] = (rr < N) ? batch[rr] : -1;
            }
            #pragma unroll
            for (int mt = 0; mt < 2; mt++) {
                int lr = wm * 32 + mt * 16 + fr;
                #pragma unroll
                for (int nt = 0; nt < 4; nt++) {
                    int col = wn * 32 + nt * 8 + 2 * fc;
                    float2 bb = *(const float2*)&bias[col];
                    float2 o0, o1;
                    o0.x = fmaxf(acc[mt][nt][0] + bb.x, 0.f);
                    o0.y = fmaxf(acc[mt][nt][1] + bb.y, 0.f);
                    o1.x = fmaxf(acc[mt][nt][2] + bb.x, 0.f);
                    o1.y = fmaxf(acc[mt][nt][3] + bb.y, 0.f);
                    *(float2*)&sInF[lr * 130 + col]       = o0;
                    *(float2*)&sInF[(lr + 8) * 130 + col] = o1;
                }
            }
            __syncthreads();
            {
                int m = min(64, N - row0);
                int col  = tid & 127;
                int half = tid >> 7;
                int rs = half * 32;
                int re = min(m, rs + 32);
                if (rs < re) {
                    float acs = 0.f;
                    int cur = sb[rs];
                    for (int r = rs; r < re; r++) {
                        int g = sb[r];
                        float v = sInF[r * 130 + col];
                        if (g != cur) {
                            atomicAdd(&g_sums[cur * 128 + col], acs);
                            acs = 0.f; cur = g;
                        }
                        acs += v;
                    }
                    atomicAdd(&g_sums[cur * 128 + col], acs);
                }
            }
            __syncthreads();
            if (ntile < num_tiles) {
                if (!PF) loadTile(ntile);
                storeTile();
            }
            __syncthreads();
        } else {
            if (ntile < num_tiles) {
                if (!PF) loadTile(ntile);
                storeTile();
            }
            __syncthreads();
            #pragma unroll
            for (int mt = 0; mt < 2; mt++) {
                int r1 = row0 + wm * 32 + mt * 16 + fr;
                #pragma unroll
                for (int nt = 0; nt < 4; nt++) {
                    int col = wn * 32 + nt * 8 + 2 * fc;
                    float2 bb = *(const float2*)&bias[col];
                    if (r1 < N) {
                        float2 o;
                        o.x = fmaxf(acc[mt][nt][0] + bb.x, 0.f);
                        o.y = fmaxf(acc[mt][nt][1] + bb.y, 0.f);
                        out[(size_t)r1 * 64 + (col >> 1)] = __float22half2_rn(o);
                    }
                    if (r1 + 8 < N) {
                        float2 o;
                        o.x = fmaxf(acc[mt][nt][2] + bb.x, 0.f);
                        o.y = fmaxf(acc[mt][nt][3] + bb.y, 0.f);
                        out[(size_t)(r1 + 8) * 64 + (col >> 1)] = __float22half2_rn(o);
                    }
                }
            }
        }
    }
}

// ---------------- MLP head + softmax (one block per graph) -------------------
__global__ void head_kernel(const float* __restrict__ fc1w, const float* __restrict__ fc1b,
                            const float* __restrict__ fc2w, const float* __restrict__ fc2b,
                            float* __restrict__ out) {
    __shared__ float p[128];
    __shared__ float hdn[128];
    __shared__ float lg[ASSETS];
    __shared__ float smax, ssum;
    int g = blockIdx.x, t = threadIdx.x;

    float cnt = fmaxf((float)(g_gend[g] - g_gstart[g]), 1.f);
    p[t] = g_sums[g * 128 + t] / cnt;
    __syncthreads();

    float a = fc1b[t];
    #pragma unroll 8
    for (int k = 0; k < 128; k++) a = fmaf(p[k], fc1w[k * 128 + t], a);
    hdn[t] = fmaxf(a, 0.f);
    __syncthreads();

    float logit = 0.f;
    if (t < ASSETS) {
        logit = fc2b[t];
        #pragma unroll 8
        for (int k = 0; k < 128; k++) logit = fmaf(hdn[k], fc2w[k * ASSETS + t], logit);
        lg[t] = logit;
    }
    __syncthreads();
    if (t == 0) {
        float m = -1e30f;
        for (int i = 0; i < ASSETS; i++) m = fmaxf(m, lg[i]);
        smax = m;
    }
    __syncthreads();
    float e = 0.f;
    if (t < ASSETS) { e = expf(logit - smax); lg[t] = e; }
    __syncthreads();
    if (t == 0) {
        float s = 0.f;
        for (int i = 0; i < ASSETS; i++) s += lg[i];
        ssum = s;
    }
    __syncthreads();
    if (t < ASSETS) out[g * ASSETS + t] = lg[t] / ssum;
}

// ---------------- launch -----------------------------------------------------
extern "C" void kernel_launch(void* const* d_in, const int* in_sizes, int n_in,
                              void* d_out, int out_size) {
    const float* x       = (const float*)d_in[0];
    const int*   ei      = (const int*)d_in[1];
    const int*   batch   = (const int*)d_in[2];
    const float* w1_rel  = (const float*)d_in[3];
    const float* b1      = (const float*)d_in[4];
    const float* w1_root = (const float*)d_in[5];
    const float* w2_rel  = (const float*)d_in[6];
    const float* b2      = (const float*)d_in[7];
    const float* w2_root = (const float*)d_in[8];
    const float* fc1w    = (const float*)d_in[9];
    const float* fc1b    = (const float*)d_in[10];
    const float* fc2w    = (const float*)d_in[11];
    const float* fc2b    = (const float*)d_in[12];
    float*       out     = (float*)d_out;

    const int N = in_sizes[2];        // 100000
    const int E = in_sizes[1] / 2;    // 1600000
    const int* src = ei;
    const int* dst = ei + E;

    void *xh, *agg1h, *h1h, *agg2h;
    cudaGetSymbolAddress(&xh,    g_xh);
    cudaGetSymbolAddress(&agg1h, g_agg1h);
    cudaGetSymbolAddress(&h1h,   g_h1h);
    cudaGetSymbolAddress(&agg2h, g_agg2h);

    const int SMEM1 = 192 * (64  + 4) * 4;   // 52224 B
    const int SMEM2 = 192 * (128 + 4) * 4;   // 101376 B
    cudaFuncSetAttribute((const void*)gemm_dual_fp16<64, true, false>,
                         cudaFuncAttributeMaxDynamicSharedMemorySize, SMEM1);
    cudaFuncSetAttribute((const void*)gemm_dual_fp16<128, true, true>,
                         cudaFuncAttributeMaxDynamicSharedMemorySize, SMEM2);

    // ---- init + CSR build ----
    init_kernel<<<512, 256>>>((const float2*)x, N * 32, N);
    hist_kernel<<<(E + 255) / 256, 256>>>(dst, E);
    int nscan = (N + 1023) / 1024;
    scan_local<<<nscan, 256>>>(N);
    scan_add<<<(N + 255) / 256, 256>>>(N, E, batch, nscan);
    fill_csr<<<(E + 255) / 256, 256>>>(src, dst, E);

    // ---- layer 1 ----
    int gblocks = (N * 32 + 255) / 256;
    gather64h<<<gblocks, 256>>>(N);

    int tiles = (N + 63) / 64;
    int grid = tiles < 296 ? tiles : 296;
    gemm_dual_fp16<64, true, false><<<grid, 256, SMEM1>>>(
        (const __half*)agg1h, (const __half*)xh, w1_rel, w1_root, b1,
        (__half2*)h1h, nullptr, N, tiles);

    // ---- layer 2 (pool fused into epilogue) ----
    gather128h<<<gblocks, 256>>>(N);

    gemm_dual_fp16<128, true, true><<<grid, 256, SMEM2>>>(
        (const __half*)agg2h, (const __half*)h1h, w2_rel, w2_root, b2,
        nullptr, batch, N, tiles);

    // ---- head ----
    head_kernel<<<GG, 128>>>(fc1w, fc1b, fc2w, fc2b, out);
}